// round 1
// baseline (speedup 1.0000x reference)
#include <cuda_runtime.h>

#define BB 8
#define NN 2048
#define CC 128
#define KK 512

typedef unsigned long long ull;

// Scratch (device globals: no allocations allowed in kernel_launch)
__device__ float g_h[BB * NN * CC];      // 8 MB: h = x@W
__device__ float g_s1[BB * NN];
__device__ float g_s2[BB * NN];
__device__ float g_maxs2[BB];
__device__ float g_hp[BB * CC];          // relu(column-mean of h) per batch
__device__ int   g_sel[BB * KK];         // ascending selected row ids per batch
__device__ unsigned char g_mask[BB * NN];

__device__ __forceinline__ float lrelu(float v) { return v >= 0.f ? v : 0.01f * v; }

// ---------------------------------------------------------------------------
// Kernel A: h = x @ W   (8 rows per block, W column slice reused across rows)
// ---------------------------------------------------------------------------
__global__ void __launch_bounds__(128) k_h(const float* __restrict__ x,
                                           const float* __restrict__ W) {
    __shared__ float xs[8][128];
    int t = threadIdx.x;
    long row0 = (long)blockIdx.x * 8;
#pragma unroll
    for (int r = 0; r < 8; r++) xs[r][t] = x[(row0 + r) * CC + t];
    __syncthreads();

    float acc[8];
#pragma unroll
    for (int r = 0; r < 8; r++) acc[r] = 0.f;

#pragma unroll 8
    for (int k = 0; k < 128; k += 4) {
        float w0 = W[(k + 0) * CC + t];
        float w1 = W[(k + 1) * CC + t];
        float w2 = W[(k + 2) * CC + t];
        float w3 = W[(k + 3) * CC + t];
#pragma unroll
        for (int r = 0; r < 8; r++) {
            float4 xv = *(const float4*)&xs[r][k];
            acc[r] = fmaf(xv.x, w0, acc[r]);
            acc[r] = fmaf(xv.y, w1, acc[r]);
            acc[r] = fmaf(xv.z, w2, acc[r]);
            acc[r] = fmaf(xv.w, w3, acc[r]);
        }
    }
#pragma unroll
    for (int r = 0; r < 8; r++) g_h[(row0 + r) * CC + t] = acc[r];
}

// ---------------------------------------------------------------------------
// Kernel A2: s1 = h@a1, s2 = h@a2   (one warp per row)
// ---------------------------------------------------------------------------
__global__ void __launch_bounds__(256) k_s(const float* __restrict__ a) {
    int t = threadIdx.x;
    int row = blockIdx.x * 8 + (t >> 5);
    int lane = t & 31;
    const float* hr = g_h + (long)row * CC;
    float p1 = 0.f, p2 = 0.f;
#pragma unroll
    for (int q = 0; q < 4; q++) {
        float hv = hr[lane + 32 * q];
        p1 = fmaf(hv, a[lane + 32 * q], p1);
        p2 = fmaf(hv, a[CC + lane + 32 * q], p2);
    }
#pragma unroll
    for (int o = 16; o; o >>= 1) {
        p1 += __shfl_xor_sync(0xffffffffu, p1, o);
        p2 += __shfl_xor_sync(0xffffffffu, p2, o);
    }
    if (lane == 0) { g_s1[row] = p1; g_s2[row] = p2; }
}

// ---------------------------------------------------------------------------
// Kernel B1: exact top-512 membership of s1[b,:] by rank counting.
// Composite 64-bit key (orderable float bits << 11 | (N-1-i)) reproduces
// top_k's (value desc, index asc) tie-break exactly; ranks are a permutation
// so exactly 512 rows are selected.
// grid = (8 sub-blocks of 256 rows, B)
// ---------------------------------------------------------------------------
__global__ void __launch_bounds__(256) k_rank() {
    int b = blockIdx.y;
    int t = threadIdx.x;
    __shared__ ull ck[NN];
    for (int idx = t; idx < NN; idx += 256) {
        unsigned u = __float_as_uint(g_s1[b * NN + idx]);
        unsigned key = (u & 0x80000000u) ? ~u : (u | 0x80000000u);
        ck[idx] = ((ull)key << 11) | (unsigned)(NN - 1 - idx);
    }
    __syncthreads();
    int i = blockIdx.x * 256 + t;
    ull me = ck[i];
    int rank = 0;
#pragma unroll 8
    for (int j = 0; j < NN; j++) rank += (ck[j] > me) ? 1 : 0;
    g_mask[b * NN + i] = (rank < KK) ? 1 : 0;
}

// ---------------------------------------------------------------------------
// Kernel B2: per batch — max(s2), ascending compaction of selected rows,
// and hp = relu(mean_j h[b,j,:]) (the shared output of all masked rows).
// grid = B blocks of 256 threads.
// ---------------------------------------------------------------------------
__global__ void __launch_bounds__(256) k_prep() {
    int b = blockIdx.x;
    int t = threadIdx.x;
    __shared__ float red[256];
    __shared__ int cnts[256];
    __shared__ int offs[256];

    // max over s2[b,:]
    float m = -3.4e38f;
    for (int idx = t; idx < NN; idx += 256) m = fmaxf(m, g_s2[b * NN + idx]);
    red[t] = m;
    __syncthreads();
    for (int o = 128; o; o >>= 1) {
        if (t < o) red[t] = fmaxf(red[t], red[t + o]);
        __syncthreads();
    }
    if (t == 0) g_maxs2[b] = red[0];

    // compaction (ascending i order preserved)
    int base = t * 8;
    unsigned char f[8];
    int c = 0;
#pragma unroll
    for (int r = 0; r < 8; r++) { f[r] = g_mask[b * NN + base + r]; c += f[r]; }
    cnts[t] = c;
    __syncthreads();
    if (t == 0) {
        int s = 0;
        for (int q = 0; q < 256; q++) { offs[q] = s; s += cnts[q]; }
    }
    __syncthreads();
    int pos = offs[t];
#pragma unroll
    for (int r = 0; r < 8; r++)
        if (f[r]) g_sel[b * KK + pos++] = base + r;

    // column mean of h[b] -> relu
    __syncthreads();
    int cc = t & 127, half = t >> 7;
    float s = 0.f;
    for (int j = half; j < NN; j += 2) s += g_h[((long)b * NN + j) * CC + cc];
    red[t] = s;
    __syncthreads();
    if (half == 0) {
        float tot = red[t] + red[t + 128];
        g_hp[b * CC + cc] = fmaxf(tot * (1.0f / NN), 0.f);
    }
}

// ---------------------------------------------------------------------------
// Kernel C: attention for the 512 selected rows per batch.
// Block = 256 thr (8 warps), 2 selected rows per warp, h tiled 64x128 in smem,
// packed f32x2 FMA accumulation (each h load feeds both rows' accumulators).
// grid = (32, B)
// ---------------------------------------------------------------------------
__global__ void __launch_bounds__(256) k_attn(float* __restrict__ out) {
    int b = blockIdx.y;
    int t = threadIdx.x, warp = t >> 5, lane = t & 31;
    __shared__ float hs[64 * CC];   // 32 KB
    __shared__ float s2s[NN];       // 8 KB

    for (int idx = t; idx < NN; idx += 256) s2s[idx] = g_s2[b * NN + idx];

    int slot = blockIdx.x * 16 + warp * 2;
    int i0 = g_sel[b * KK + slot];
    int i1 = g_sel[b * KK + slot + 1];
    float ms2 = g_maxs2[b];
    float s10 = g_s1[b * NN + i0], s11 = g_s1[b * NN + i1];
    float M0 = lrelu(s10 + ms2), M1 = lrelu(s11 + ms2);

    ull a00 = 0, a01 = 0, a10 = 0, a11 = 0;   // packed f32x2 accumulators
    float Z0 = 0.f, Z1 = 0.f;
    const float* hb = g_h + (long)b * NN * CC;

    for (int jt = 0; jt < NN; jt += 64) {
        __syncthreads();
        const float4* src = (const float4*)(hb + jt * CC);
        float4* dst = (float4*)hs;
#pragma unroll
        for (int r = 0; r < 8; r++) dst[r * 256 + t] = src[r * 256 + t];
        __syncthreads();

#pragma unroll
        for (int jj = 0; jj < 64; jj += 32) {
            float v = s2s[jt + jj + lane];
            float w0 = __expf(lrelu(s10 + v) - M0);
            float w1 = __expf(lrelu(s11 + v) - M1);
            Z0 += w0; Z1 += w1;
#pragma unroll
            for (int tt = 0; tt < 32; tt++) {
                float w0t = __shfl_sync(0xffffffffu, w0, tt);
                float w1t = __shfl_sync(0xffffffffu, w1, tt);
                ull w0p, w1p;
                asm("mov.b64 %0, {%1, %1};" : "=l"(w0p) : "f"(w0t));
                asm("mov.b64 %0, {%1, %1};" : "=l"(w1p) : "f"(w1t));
                const ull* hp64 = (const ull*)(hs + (jj + tt) * CC);
                ull hv0 = hp64[lane];
                ull hv1 = hp64[lane + 32];
                asm("fma.rn.f32x2 %0, %1, %2, %0;" : "+l"(a00) : "l"(w0p), "l"(hv0));
                asm("fma.rn.f32x2 %0, %1, %2, %0;" : "+l"(a01) : "l"(w0p), "l"(hv1));
                asm("fma.rn.f32x2 %0, %1, %2, %0;" : "+l"(a10) : "l"(w1p), "l"(hv0));
                asm("fma.rn.f32x2 %0, %1, %2, %0;" : "+l"(a11) : "l"(w1p), "l"(hv1));
            }
        }
    }

#pragma unroll
    for (int o = 16; o; o >>= 1) {
        Z0 += __shfl_xor_sync(0xffffffffu, Z0, o);
        Z1 += __shfl_xor_sync(0xffffffffu, Z1, o);
    }
    float r0 = 1.f / Z0, r1 = 1.f / Z1;

    float lo, hi;
    float* ob = out + (long)b * CC * NN;
    asm("mov.b64 {%0, %1}, %2;" : "=f"(lo), "=f"(hi) : "l"(a00));
    ob[(2 * lane) * NN + i0]      = fmaxf(lo * r0, 0.f);
    ob[(2 * lane + 1) * NN + i0]  = fmaxf(hi * r0, 0.f);
    asm("mov.b64 {%0, %1}, %2;" : "=f"(lo), "=f"(hi) : "l"(a01));
    ob[(64 + 2 * lane) * NN + i0] = fmaxf(lo * r0, 0.f);
    ob[(65 + 2 * lane) * NN + i0] = fmaxf(hi * r0, 0.f);
    asm("mov.b64 {%0, %1}, %2;" : "=f"(lo), "=f"(hi) : "l"(a10));
    ob[(2 * lane) * NN + i1]      = fmaxf(lo * r1, 0.f);
    ob[(2 * lane + 1) * NN + i1]  = fmaxf(hi * r1, 0.f);
    asm("mov.b64 {%0, %1}, %2;" : "=f"(lo), "=f"(hi) : "l"(a11));
    ob[(64 + 2 * lane) * NN + i1] = fmaxf(lo * r1, 0.f);
    ob[(65 + 2 * lane) * NN + i1] = fmaxf(hi * r1, 0.f);
}

// ---------------------------------------------------------------------------
// Kernel D: masked rows all get the shared relu(mean h) vector.
// out layout: out[b][c][i], i in the low 11 bits -> coalesced.
// ---------------------------------------------------------------------------
__global__ void __launch_bounds__(256) k_fill(float* __restrict__ out) {
    int idx = blockIdx.x * 256 + threadIdx.x;
    int i = idx & (NN - 1);
    int c = (idx >> 11) & (CC - 1);
    int b = idx >> 18;
    if (!g_mask[b * NN + i]) out[idx] = g_hp[b * CC + c];
}

// ---------------------------------------------------------------------------
extern "C" void kernel_launch(void* const* d_in, const int* in_sizes, int n_in,
                              void* d_out, int out_size) {
    // Identify inputs by element count (all four sizes are distinct):
    // x: 8*2048*128 = 2097152, W: 128*128 = 16384, a: 256, GL: 2048*128 = 262144 (unused)
    const float* x = nullptr;
    const float* W = nullptr;
    const float* a = nullptr;
    for (int k = 0; k < n_in; k++) {
        if (in_sizes[k] == BB * NN * CC)      x = (const float*)d_in[k];
        else if (in_sizes[k] == CC * CC)      W = (const float*)d_in[k];
        else if (in_sizes[k] == 2 * CC)       a = (const float*)d_in[k];
    }
    float* out = (float*)d_out;

    k_h   <<<BB * NN / 8, 128>>>(x, W);
    k_s   <<<BB * NN / 8, 256>>>(a);
    k_rank<<<dim3(8, BB), 256>>>();
    k_prep<<<BB, 256>>>();
    k_attn<<<dim3(32, BB), 256>>>(out);
    k_fill<<<BB * CC * NN / 256, 256>>>(out);
}

// round 2
// speedup vs baseline: 1.3603x; 1.3603x over previous
#include <cuda_runtime.h>

#define BB 8
#define NN 2048
#define CC 128
#define KK 512

typedef unsigned long long ull;

// Scratch (device globals: no allocations allowed)
__device__ float g_h[BB * NN * CC];      // 8 MB: h = x@W
__device__ float g_s1[BB * NN];
__device__ float g_s2[BB * NN];
__device__ float g_maxs2[BB];
__device__ float g_hp[BB * CC];          // relu(column-mean of h) per batch
__device__ float g_xpart[BB * 16 * CC];  // partial column sums of x
__device__ int   g_rank[BB * NN];
__device__ int   g_sel[BB * KK];         // ascending selected row ids per batch
__device__ unsigned char g_mask[BB * NN];

__device__ __forceinline__ float lrelu(float v) { return v >= 0.f ? v : 0.01f * v; }

// ---------------------------------------------------------------------------
// Kernel A: h = x @ W   (8 rows per block)
// ---------------------------------------------------------------------------
__global__ void __launch_bounds__(128) k_h(const float* __restrict__ x,
                                           const float* __restrict__ W) {
    __shared__ float xs[8][128];
    int t = threadIdx.x;
    long row0 = (long)blockIdx.x * 8;
#pragma unroll
    for (int r = 0; r < 8; r++) xs[r][t] = x[(row0 + r) * CC + t];
    __syncthreads();

    float acc[8];
#pragma unroll
    for (int r = 0; r < 8; r++) acc[r] = 0.f;

#pragma unroll 8
    for (int k = 0; k < 128; k += 4) {
        float w0 = W[(k + 0) * CC + t];
        float w1 = W[(k + 1) * CC + t];
        float w2 = W[(k + 2) * CC + t];
        float w3 = W[(k + 3) * CC + t];
#pragma unroll
        for (int r = 0; r < 8; r++) {
            float4 xv = *(const float4*)&xs[r][k];
            acc[r] = fmaf(xv.x, w0, acc[r]);
            acc[r] = fmaf(xv.y, w1, acc[r]);
            acc[r] = fmaf(xv.z, w2, acc[r]);
            acc[r] = fmaf(xv.w, w3, acc[r]);
        }
    }
#pragma unroll
    for (int r = 0; r < 8; r++) g_h[(row0 + r) * CC + t] = acc[r];
}

// ---------------------------------------------------------------------------
// Kernel A2: s1 = h@a1, s2 = h@a2 (one warp per row); also zeroes g_rank.
// ---------------------------------------------------------------------------
__global__ void __launch_bounds__(256) k_s(const float* __restrict__ a) {
    int t = threadIdx.x;
    int row = blockIdx.x * 8 + (t >> 5);
    int lane = t & 31;
    const float* hr = g_h + (long)row * CC;
    float p1 = 0.f, p2 = 0.f;
#pragma unroll
    for (int q = 0; q < 4; q++) {
        float hv = hr[lane + 32 * q];
        p1 = fmaf(hv, a[lane + 32 * q], p1);
        p2 = fmaf(hv, a[CC + lane + 32 * q], p2);
    }
#pragma unroll
    for (int o = 16; o; o >>= 1) {
        p1 += __shfl_xor_sync(0xffffffffu, p1, o);
        p2 += __shfl_xor_sync(0xffffffffu, p2, o);
    }
    if (lane == 0) { g_s1[row] = p1; g_s2[row] = p2; g_rank[row] = 0; }
}

// ---------------------------------------------------------------------------
// Kernel X: partial column sums of x (for colmean(h) = colmean(x) @ W).
// grid (16 row-chunks, B), 256 threads.
// ---------------------------------------------------------------------------
__global__ void __launch_bounds__(256) k_xpart(const float* __restrict__ x) {
    int b = blockIdx.y, chunk = blockIdx.x;
    int t = threadIdx.x;
    int c = t & 127, h2 = t >> 7;
    const float* xb = x + ((long)b * NN + chunk * 128) * CC;
    float s = 0.f;
    for (int r = h2; r < 128; r += 2) s += xb[(long)r * CC + c];
    __shared__ float red[256];
    red[t] = s;
    __syncthreads();
    if (h2 == 0) g_xpart[(b * 16 + chunk) * CC + c] = red[c] + red[c + 128];
}

// ---------------------------------------------------------------------------
// Kernel B1: partial rank counting, tiled over i and j.
// Composite 64-bit key reproduces top_k (value desc, index asc) exactly.
// grid (8 i-chunks, 8 j-chunks, B). Integer atomics => deterministic.
// ---------------------------------------------------------------------------
__device__ __forceinline__ ull rankkey(int b, int idx) {
    unsigned u = __float_as_uint(g_s1[b * NN + idx]);
    unsigned key = (u & 0x80000000u) ? ~u : (u | 0x80000000u);
    return ((ull)key << 11) | (unsigned)(NN - 1 - idx);
}

__global__ void __launch_bounds__(256) k_rank() {
    int b = blockIdx.z;
    int t = threadIdx.x;
    __shared__ ull jk[256];
    jk[t] = rankkey(b, blockIdx.y * 256 + t);
    __syncthreads();
    int i = blockIdx.x * 256 + t;
    ull me = rankkey(b, i);
    int cnt = 0;
#pragma unroll 16
    for (int j = 0; j < 256; j++) cnt += (jk[j] > me) ? 1 : 0;
    atomicAdd(&g_rank[b * NN + i], cnt);
}

// ---------------------------------------------------------------------------
// Kernel B2: per batch — mask from ranks, max(s2), ascending compaction,
// and hp = relu((colmean x) @ W).
// ---------------------------------------------------------------------------
__global__ void __launch_bounds__(256) k_prep(const float* __restrict__ W) {
    int b = blockIdx.x;
    int t = threadIdx.x;
    __shared__ float red[256];
    __shared__ int cnts[256];
    __shared__ int offs[256];
    __shared__ float xm[128];

    // max over s2[b,:]
    float m = -3.4e38f;
    for (int idx = t; idx < NN; idx += 256) m = fmaxf(m, g_s2[b * NN + idx]);
    red[t] = m;
    __syncthreads();
    for (int o = 128; o; o >>= 1) {
        if (t < o) red[t] = fmaxf(red[t], red[t + o]);
        __syncthreads();
    }
    if (t == 0) g_maxs2[b] = red[0];

    // mask + compaction (ascending i preserved)
    int base = t * 8;
    unsigned char f[8];
    int c = 0;
#pragma unroll
    for (int r = 0; r < 8; r++) {
        f[r] = (g_rank[b * NN + base + r] < KK) ? 1 : 0;
        g_mask[b * NN + base + r] = f[r];
        c += f[r];
    }
    cnts[t] = c;
    __syncthreads();
    if (t == 0) {
        int s = 0;
        for (int q = 0; q < 256; q++) { offs[q] = s; s += cnts[q]; }
    }
    __syncthreads();
    int pos = offs[t];
#pragma unroll
    for (int r = 0; r < 8; r++)
        if (f[r]) g_sel[b * KK + pos++] = base + r;

    // hp = relu( (colmean x) @ W )
    if (t < 128) {
        float s = 0.f;
#pragma unroll
        for (int k = 0; k < 16; k++) s += g_xpart[(b * 16 + k) * CC + t];
        xm[t] = s * (1.0f / NN);
    }
    __syncthreads();
    if (t < 128) {
        float acc = 0.f;
#pragma unroll 8
        for (int k = 0; k < 128; k++) acc = fmaf(xm[k], W[k * CC + t], acc);
        g_hp[b * CC + t] = fmaxf(acc, 0.f);
    }
}

// ---------------------------------------------------------------------------
// Kernel C: attention over the 512 selected rows.
// 128 thr (4 warps), 4 rows/warp, 4 cols/lane via one LDS.128 per j.
// grid (32, B) = 256 blocks; smem 40KB -> 2 blocks/SM, single wave.
// ---------------------------------------------------------------------------
__global__ void __launch_bounds__(128) k_attn(float* __restrict__ out) {
    int b = blockIdx.y;
    int t = threadIdx.x, warp = t >> 5, lane = t & 31;
    __shared__ float hs[64 * CC];   // 32 KB
    __shared__ float s2s[NN];       // 8 KB

    for (int idx = t; idx < NN; idx += 128) s2s[idx] = g_s2[b * NN + idx];

    int slot = blockIdx.x * 16 + warp * 4;
    int rows[4];
    float s1r[4], Mr[4], Z[4];
    float ms2 = g_maxs2[b];
#pragma unroll
    for (int r = 0; r < 4; r++) {
        rows[r] = g_sel[b * KK + slot + r];
        s1r[r] = g_s1[b * NN + rows[r]];
        Mr[r] = lrelu(s1r[r] + ms2);
        Z[r] = 0.f;
    }

    ull acc[4][2];
#pragma unroll
    for (int r = 0; r < 4; r++) { acc[r][0] = 0; acc[r][1] = 0; }

    const float* hb = g_h + (long)b * NN * CC;

    for (int jt = 0; jt < NN; jt += 64) {
        __syncthreads();
        const float4* src = (const float4*)(hb + (long)jt * CC);
        float4* dst = (float4*)hs;
#pragma unroll
        for (int r = 0; r < 16; r++) dst[r * 128 + t] = src[r * 128 + t];
        __syncthreads();

#pragma unroll
        for (int jj = 0; jj < 64; jj += 32) {
            float v = s2s[jt + jj + lane];
            float w[4];
#pragma unroll
            for (int r = 0; r < 4; r++) {
                w[r] = __expf(lrelu(s1r[r] + v) - Mr[r]);
                Z[r] += w[r];
            }
#pragma unroll
            for (int tt = 0; tt < 32; tt++) {
                ulonglong2 hv = *(const ulonglong2*)(hs + (jj + tt) * CC + 4 * lane);
#pragma unroll
                for (int r = 0; r < 4; r++) {
                    float wt = __shfl_sync(0xffffffffu, w[r], tt);
                    ull wp;
                    asm("mov.b64 %0, {%1, %1};" : "=l"(wp) : "f"(wt));
                    asm("fma.rn.f32x2 %0, %1, %2, %0;" : "+l"(acc[r][0]) : "l"(wp), "l"(hv.x));
                    asm("fma.rn.f32x2 %0, %1, %2, %0;" : "+l"(acc[r][1]) : "l"(wp), "l"(hv.y));
                }
            }
        }
    }

#pragma unroll
    for (int r = 0; r < 4; r++)
#pragma unroll
        for (int o = 16; o; o >>= 1)
            Z[r] += __shfl_xor_sync(0xffffffffu, Z[r], o);

    float* ob = out + (long)b * CC * NN;
#pragma unroll
    for (int r = 0; r < 4; r++) {
        float rinv = 1.f / Z[r];
        int i = rows[r];
        float lo, hi;
        asm("mov.b64 {%0, %1}, %2;" : "=f"(lo), "=f"(hi) : "l"(acc[r][0]));
        ob[(4 * lane + 0) * NN + i] = fmaxf(lo * rinv, 0.f);
        ob[(4 * lane + 1) * NN + i] = fmaxf(hi * rinv, 0.f);
        asm("mov.b64 {%0, %1}, %2;" : "=f"(lo), "=f"(hi) : "l"(acc[r][1]));
        ob[(4 * lane + 2) * NN + i] = fmaxf(lo * rinv, 0.f);
        ob[(4 * lane + 3) * NN + i] = fmaxf(hi * rinv, 0.f);
    }
}

// ---------------------------------------------------------------------------
// Kernel D: masked rows get the shared relu(colmean h) vector.
// ---------------------------------------------------------------------------
__global__ void __launch_bounds__(256) k_fill(float* __restrict__ out) {
    int idx = blockIdx.x * 256 + threadIdx.x;
    int i = idx & (NN - 1);
    int c = (idx >> 11) & (CC - 1);
    int b = idx >> 18;
    if (!g_mask[b * NN + i]) out[idx] = g_hp[b * CC + c];
}

// ---------------------------------------------------------------------------
extern "C" void kernel_launch(void* const* d_in, const int* in_sizes, int n_in,
                              void* d_out, int out_size) {
    // x: 2097152, W: 16384, a: 256, GL: 262144 (unused)
    const float* x = nullptr;
    const float* W = nullptr;
    const float* a = nullptr;
    for (int k = 0; k < n_in; k++) {
        if (in_sizes[k] == BB * NN * CC)      x = (const float*)d_in[k];
        else if (in_sizes[k] == CC * CC)      W = (const float*)d_in[k];
        else if (in_sizes[k] == 2 * CC)       a = (const float*)d_in[k];
    }
    float* out = (float*)d_out;

    k_h    <<<BB * NN / 8, 128>>>(x, W);
    k_xpart<<<dim3(16, BB), 256>>>(x);
    k_s    <<<BB * NN / 8, 256>>>(a);
    k_rank <<<dim3(8, 8, BB), 256>>>();
    k_prep <<<BB, 256>>>(W);
    k_attn <<<dim3(32, BB), 256 / 2>>>(out);
    k_fill <<<BB * CC * NN / 256, 256>>>(out);
}